// round 16
// baseline (speedup 1.0000x reference)
#include <cuda_runtime.h>
#include <math.h>

#define T_LEN    4096
#define NTHREADS 256
#define NSEG     4               // segments of 1024 elements
#define NWARPS   (NTHREADS / 32)
#define FULL     0xFFFFFFFFu

__global__ __launch_bounds__(NTHREADS, 6)
void garch_kernel(const float4* __restrict__ x4,
                  const float* __restrict__ omega_log,
                  const float* __restrict__ alpha_log,
                  const float* __restrict__ beta_log,
                  float4* __restrict__ out4)
{
    __shared__ float BwS[NSEG][NWARPS];   // per-segment cross-warp B scan
    __shared__ float sumw[NWARPS], sqw[NWARPS];
    __shared__ float s0_sh;

    const int tid  = threadIdx.x;
    const int lane = tid & 31;
    const int wid  = tid >> 5;

    // ---- scalar params ----
    const float ea    = expf(alpha_log[0]);
    const float eb    = expf(beta_log[0]);
    const float denom = 1.0f + ea + eb;
    const float omega = expf(omega_log[0]);
    const float alpha = ea / denom;
    const float beta  = eb / denom;

    // scan multipliers: beta^(4*2^i) by repeated squaring (die after the scan)
    float m0 = beta * beta;  m0 = m0 * m0;      // beta^4
    const float m1 = m0 * m0;                   // beta^8
    const float m2 = m1 * m1;                   // beta^16
    const float m3 = m2 * m2;                   // beta^32
    const float m4 = m3 * m3;                   // beta^64
    const float p128_1 = m4 * m4;               // beta^128
    const float p128_2 = p128_1 * p128_1;       // beta^256
    const float p128_4 = p128_2 * p128_2;       // beta^512
    const float beta1024 = p128_4 * p128_4;     // beta^1024 (segment A)

    // exclusive-prefix factors via MUFU (replaces predicated power chains)
    const float lnb   = __logf(beta);
    const float a_exc = __expf((float)(4 * lane) * lnb);   // beta^(4*lane)
    const float a_tot = __expf((float)(4 * tid)  * lnb);   // beta^(4*tid)

    // ---- load: 4 coalesced float4 per thread (the float4 IS the chunk) ----
    const size_t row4 = (size_t)blockIdx.x * (NSEG * NTHREADS);
    float4 v[NSEG];
    #pragma unroll
    for (int j = 0; j < NSEG; j++)
        v[j] = __ldcs(&x4[row4 + j * NTHREADS + tid]);

    // ---- variance partials + c_t = alpha*x_t^2 + omega ----
    float c[NSEG][4];
    float sum = 0.0f, sq = 0.0f;
    #pragma unroll
    for (int j = 0; j < NSEG; j++) {
        float xs[4] = { v[j].x, v[j].y, v[j].z, v[j].w };
        #pragma unroll
        for (int k = 0; k < 4; k++) {
            float x2 = xs[k] * xs[k];
            sum += xs[k];
            sq  += x2;
            c[j][k] = fmaf(alpha, x2, omega);
        }
    }
    #pragma unroll
    for (int off = 16; off > 0; off >>= 1) {
        sum += __shfl_xor_sync(FULL, sum, off);
        sq  += __shfl_xor_sync(FULL, sq,  off);
    }
    if (lane == 0) { sumw[wid] = sum; sqw[wid] = sq; }

    // ---- per-segment local B over 4 steps (A = beta^4, constant) ----
    float B[NSEG];
    #pragma unroll
    for (int j = 0; j < NSEG; j++) {
        float b = c[j][0];
        b = fmaf(beta, b, c[j][1]);
        b = fmaf(beta, b, c[j][2]);
        b = fmaf(beta, b, c[j][3]);
        B[j] = b;
    }

    // ---- B-only warp scans, constant multiplier per step: beta^(4*off) ----
    {
        const float mult[5] = { m0, m1, m2, m3, m4 };
        #pragma unroll
        for (int i = 0; i < 5; i++) {
            const int off = 1 << i;
            float bu[NSEG];
            #pragma unroll
            for (int j = 0; j < NSEG; j++)
                bu[j] = __shfl_up_sync(FULL, B[j], off);
            if (lane >= off) {
                #pragma unroll
                for (int j = 0; j < NSEG; j++)
                    B[j] = fmaf(mult[i], bu[j], B[j]);
            }
        }
    }
    if (lane == 31) {
        #pragma unroll
        for (int j = 0; j < NSEG; j++) BwS[j][wid] = B[j];
    }
    __syncthreads();

    // ---- warp 0: four 8-element cross-warp B scans (multiplier beta^(128*off)) ----
    if (wid == 0) {
        const int g  = lane >> 3;
        const int l8 = lane & 7;
        float b = BwS[g][l8];
        float bu;
        bu = __shfl_up_sync(FULL, b, 1); if (l8 >= 1) b = fmaf(p128_1, bu, b);
        bu = __shfl_up_sync(FULL, b, 2); if (l8 >= 2) b = fmaf(p128_2, bu, b);
        bu = __shfl_up_sync(FULL, b, 4); if (l8 >= 4) b = fmaf(p128_4, bu, b);
        BwS[g][l8] = b;
    }
    // ---- warp 1: finish variance concurrently ----
    if (wid == 1) {
        float ts = (lane < NWARPS) ? sumw[lane] : 0.0f;
        float tq = (lane < NWARPS) ? sqw[lane]  : 0.0f;
        #pragma unroll
        for (int off = 4; off > 0; off >>= 1) {
            ts += __shfl_xor_sync(FULL, ts, off);
            tq += __shfl_xor_sync(FULL, tq, off);
        }
        if (lane == 0) {
            s0_sh = (tq - ts * ts * (1.0f / (float)T_LEN))
                    * (1.0f / (float)(T_LEN - 1));
        }
    }
    __syncthreads();
    const float s0 = s0_sh;

    // ---- segment base states: S_{j+1} = beta^1024 * S_j + Bfull_j ----
    float S[NSEG];
    S[0] = s0;
    #pragma unroll
    for (int j = 0; j < NSEG - 1; j++)
        S[j + 1] = fmaf(beta1024, S[j], BwS[j][NWARPS - 1]);

    // ---- thread-exclusive b within warp ----
    float b_exc[NSEG];
    #pragma unroll
    for (int j = 0; j < NSEG; j++) {
        b_exc[j] = __shfl_up_sync(FULL, B[j], 1);
        if (lane == 0) b_exc[j] = 0.0f;
    }

    // ---- replay all 4 segments (independent chains -> MUFU/FMA ILP) ----
    #pragma unroll
    for (int j = 0; j < NSEG; j++) {
        float b_wp = (wid > 0) ? BwS[j][wid - 1] : 0.0f;
        float s = fmaf(a_tot, S[j], fmaf(a_exc, b_wp, b_exc[j]));

        float4 o;
        o.x = s * rsqrtf(s); s = fmaf(beta, s, c[j][0]);
        o.y = s * rsqrtf(s); s = fmaf(beta, s, c[j][1]);
        o.z = s * rsqrtf(s); s = fmaf(beta, s, c[j][2]);
        o.w = s * rsqrtf(s);

        __stcs(&out4[row4 + j * NTHREADS + tid], o);
    }
}

extern "C" void kernel_launch(void* const* d_in, const int* in_sizes, int n_in,
                              void* d_out, int out_size)
{
    const float4* x4       = (const float4*)d_in[0];
    const float* omega_log = (const float*)d_in[1];
    const float* alpha_log = (const float*)d_in[2];
    const float* beta_log  = (const float*)d_in[3];
    float4* out4 = (float4*)d_out;

    const int B = in_sizes[0] / T_LEN;   // 4096 rows
    garch_kernel<<<B, NTHREADS>>>(x4, omega_log, alpha_log, beta_log, out4);
}

// round 17
// speedup vs baseline: 1.3249x; 1.3249x over previous
#include <cuda_runtime.h>
#include <math.h>

#define T_LEN    4096
#define NTHREADS 256
#define NSEG     4               // segments of 1024 elements
#define NWARPS   (NTHREADS / 32)
#define FULL     0xFFFFFFFFu

// smem param slots (block-uniform, computed by thread 0)
#define P_ALPHA    0
#define P_BETA     1
#define P_OMEGA    2
#define P_M0       3    // beta^4
#define P_M1       4    // beta^8
#define P_M2       5    // beta^16
#define P_M3       6    // beta^32
#define P_M4       7    // beta^64
#define P_P128     8    // beta^128
#define P_P256     9    // beta^256
#define P_P512     10   // beta^512
#define P_B1024    11   // beta^1024

__global__ __launch_bounds__(NTHREADS, 5)
void garch_kernel(const float4* __restrict__ x4,
                  const float* __restrict__ omega_log,
                  const float* __restrict__ alpha_log,
                  const float* __restrict__ beta_log,
                  float4* __restrict__ out4)
{
    __shared__ float prm[12];
    __shared__ float BwS[NSEG][NWARPS];   // per-segment cross-warp B scan
    __shared__ float sumw[NWARPS], sqw[NWARPS];
    __shared__ float s0_sh;

    const int tid  = threadIdx.x;
    const int lane = tid & 31;
    const int wid  = tid >> 5;

    // ---- issue the 4 coalesced loads FIRST (in flight across the param barrier) ----
    const size_t row4 = (size_t)blockIdx.x * (NSEG * NTHREADS);
    float4 v[NSEG];
    #pragma unroll
    for (int j = 0; j < NSEG; j++)
        v[j] = __ldcs(&x4[row4 + j * NTHREADS + tid]);

    // ---- thread 0 only: scalar params + beta powers -> smem ----
    if (tid == 0) {
        float ea    = expf(alpha_log[0]);
        float eb    = expf(beta_log[0]);
        float denom = 1.0f + ea + eb;
        float om    = expf(omega_log[0]);
        float al    = ea / denom;
        float be    = eb / denom;
        float t0 = be * be;
        float q0 = t0 * t0;          // beta^4
        float q1 = q0 * q0;          // beta^8
        float q2 = q1 * q1;          // beta^16
        float q3 = q2 * q2;          // beta^32
        float q4 = q3 * q3;          // beta^64
        float r1 = q4 * q4;          // beta^128
        float r2 = r1 * r1;          // beta^256
        float r4 = r2 * r2;          // beta^512
        prm[P_ALPHA] = al;  prm[P_BETA] = be;  prm[P_OMEGA] = om;
        prm[P_M0] = q0; prm[P_M1] = q1; prm[P_M2] = q2; prm[P_M3] = q3; prm[P_M4] = q4;
        prm[P_P128] = r1; prm[P_P256] = r2; prm[P_P512] = r4; prm[P_B1024] = r4 * r4;
    }
    __syncthreads();

    // broadcast LDS (conflict-free)
    const float alpha    = prm[P_ALPHA];
    const float beta     = prm[P_BETA];
    const float omega    = prm[P_OMEGA];
    const float m0       = prm[P_M0];
    const float m1       = prm[P_M1];
    const float m2       = prm[P_M2];
    const float m3       = prm[P_M3];
    const float m4       = prm[P_M4];
    const float p128_1   = prm[P_P128];
    const float p128_2   = prm[P_P256];
    const float p128_4   = prm[P_P512];
    const float beta1024 = prm[P_B1024];

    // ---- variance partials + c_t = alpha*x_t^2 + omega ----
    float c[NSEG][4];
    float sum = 0.0f, sq = 0.0f;
    #pragma unroll
    for (int j = 0; j < NSEG; j++) {
        float xs[4] = { v[j].x, v[j].y, v[j].z, v[j].w };
        #pragma unroll
        for (int k = 0; k < 4; k++) {
            float x2 = xs[k] * xs[k];
            sum += xs[k];
            sq  += x2;
            c[j][k] = fmaf(alpha, x2, omega);
        }
    }
    #pragma unroll
    for (int off = 16; off > 0; off >>= 1) {
        sum += __shfl_xor_sync(FULL, sum, off);
        sq  += __shfl_xor_sync(FULL, sq,  off);
    }
    if (lane == 0) { sumw[wid] = sum; sqw[wid] = sq; }

    // ---- per-segment local B over 4 steps (A = beta^4, constant) ----
    float B[NSEG];
    #pragma unroll
    for (int j = 0; j < NSEG; j++) {
        float b = c[j][0];
        b = fmaf(beta, b, c[j][1]);
        b = fmaf(beta, b, c[j][2]);
        b = fmaf(beta, b, c[j][3]);
        B[j] = b;
    }

    // ---- B-only warp scans, constant multiplier per step: beta^(4*off) ----
    {
        const float mult[5] = { m0, m1, m2, m3, m4 };
        #pragma unroll
        for (int i = 0; i < 5; i++) {
            const int off = 1 << i;
            float bu[NSEG];
            #pragma unroll
            for (int j = 0; j < NSEG; j++)
                bu[j] = __shfl_up_sync(FULL, B[j], off);
            if (lane >= off) {
                #pragma unroll
                for (int j = 0; j < NSEG; j++)
                    B[j] = fmaf(mult[i], bu[j], B[j]);
            }
        }
    }
    if (lane == 31) {
        #pragma unroll
        for (int j = 0; j < NSEG; j++) BwS[j][wid] = B[j];
    }
    __syncthreads();

    // ---- warp 0: four 8-element cross-warp B scans (multiplier beta^(128*off)) ----
    if (wid == 0) {
        const int g  = lane >> 3;
        const int l8 = lane & 7;
        float b = BwS[g][l8];
        float bu;
        bu = __shfl_up_sync(FULL, b, 1); if (l8 >= 1) b = fmaf(p128_1, bu, b);
        bu = __shfl_up_sync(FULL, b, 2); if (l8 >= 2) b = fmaf(p128_2, bu, b);
        bu = __shfl_up_sync(FULL, b, 4); if (l8 >= 4) b = fmaf(p128_4, bu, b);
        BwS[g][l8] = b;
    }
    // ---- warp 1: finish variance concurrently ----
    if (wid == 1) {
        float ts = (lane < NWARPS) ? sumw[lane] : 0.0f;
        float tq = (lane < NWARPS) ? sqw[lane]  : 0.0f;
        #pragma unroll
        for (int off = 4; off > 0; off >>= 1) {
            ts += __shfl_xor_sync(FULL, ts, off);
            tq += __shfl_xor_sync(FULL, tq, off);
        }
        if (lane == 0) {
            s0_sh = (tq - ts * ts * (1.0f / (float)T_LEN))
                    * (1.0f / (float)(T_LEN - 1));
        }
    }
    __syncthreads();
    const float s0 = s0_sh;

    // ---- segment base states: S_{j+1} = beta^1024 * S_j + Bfull_j ----
    float S[NSEG];
    S[0] = s0;
    #pragma unroll
    for (int j = 0; j < NSEG - 1; j++)
        S[j + 1] = fmaf(beta1024, S[j], BwS[j][NWARPS - 1]);

    // ---- exclusive prefixes: b via shuffle, a from lane/wid bits ----
    float b_exc[NSEG];
    #pragma unroll
    for (int j = 0; j < NSEG; j++) {
        b_exc[j] = __shfl_up_sync(FULL, B[j], 1);
        if (lane == 0) b_exc[j] = 0.0f;
    }
    float a_exc = 1.0f;                         // beta^(4*lane)
    if (lane & 1)  a_exc *= m0;
    if (lane & 2)  a_exc *= m1;
    if (lane & 4)  a_exc *= m2;
    if (lane & 8)  a_exc *= m3;
    if (lane & 16) a_exc *= m4;
    float a_wp = 1.0f;                          // beta^(128*wid)
    if (wid & 1) a_wp *= p128_1;
    if (wid & 2) a_wp *= p128_2;
    if (wid & 4) a_wp *= p128_4;
    const float a_tot = a_exc * a_wp;

    // ---- replay all 4 segments (independent chains -> MUFU/FMA ILP) ----
    #pragma unroll
    for (int j = 0; j < NSEG; j++) {
        float b_wp = (wid > 0) ? BwS[j][wid - 1] : 0.0f;
        float s = fmaf(a_tot, S[j], fmaf(a_exc, b_wp, b_exc[j]));

        float4 o;
        o.x = s * rsqrtf(s); s = fmaf(beta, s, c[j][0]);
        o.y = s * rsqrtf(s); s = fmaf(beta, s, c[j][1]);
        o.z = s * rsqrtf(s); s = fmaf(beta, s, c[j][2]);
        o.w = s * rsqrtf(s);

        __stcs(&out4[row4 + j * NTHREADS + tid], o);
    }
}

extern "C" void kernel_launch(void* const* d_in, const int* in_sizes, int n_in,
                              void* d_out, int out_size)
{
    const float4* x4       = (const float4*)d_in[0];
    const float* omega_log = (const float*)d_in[1];
    const float* alpha_log = (const float*)d_in[2];
    const float* beta_log  = (const float*)d_in[3];
    float4* out4 = (float4*)d_out;

    const int B = in_sizes[0] / T_LEN;   // 4096 rows
    garch_kernel<<<B, NTHREADS>>>(x4, omega_log, alpha_log, beta_log, out4);
}